// round 2
// baseline (speedup 1.0000x reference)
#include <cuda_runtime.h>

#define BB 8
#define NNODE 2048
#define DD 256
#define RR (BB*NNODE)   // 16384 total rows

// Scratch (allocation-free rule: device globals)
__device__ float g_x[BB*NNODE*DD];   // current layer activations
__device__ float g_t[BB*NNODE*DD];   // xWr
__device__ float g_u[BB*NNODE*DD];   // xW0
__device__ float g_denom[RR];

// ---------------------------------------------------------------------------
// denom[b,n] = sum_k adj[b,n,k] + 1
// ---------------------------------------------------------------------------
__global__ void denom_kernel(const float* __restrict__ adj) {
    __shared__ float red[8];
    int row = blockIdx.x;
    const float4* a = (const float4*)(adj + (size_t)row * NNODE);
    float s = 0.f;
#pragma unroll
    for (int i = 0; i < 2; i++) {
        float4 v = a[threadIdx.x + i * 256];
        s += (v.x + v.y) + (v.z + v.w);
    }
#pragma unroll
    for (int o = 16; o > 0; o >>= 1) s += __shfl_xor_sync(0xffffffffu, s, o);
    if ((threadIdx.x & 31) == 0) red[threadIdx.x >> 5] = s;
    __syncthreads();
    if (threadIdx.x < 8) {
        s = red[threadIdx.x];
#pragma unroll
        for (int o = 4; o > 0; o >>= 1) s += __shfl_xor_sync(0xffu, s, o);
        if (threadIdx.x == 0) g_denom[row] = s + 1.0f;
    }
}

// ---------------------------------------------------------------------------
// Fused dual NT GEMM: for both W in {Wr, W0}:
//   g_t[r,m] = sum_d X[r,d] * Wr[m,d] + br[m]
//   g_u[r,m] = sum_d X[r,d] * W0[m,d] + b0[m]
// X: [16384,256] row-major (nodes for layer 0, g_x for layer 1).
// Tile: BM=128, BN=64, BK=16, 256 threads, 8x4 per thread per output.
// ---------------------------------------------------------------------------
__global__ void __launch_bounds__(256, 2) dual_gemm(
    int in_sel, const float* __restrict__ nodes,
    const float* __restrict__ Wr, const float* __restrict__ br,
    const float* __restrict__ W0, const float* __restrict__ b0)
{
    const float* __restrict__ X = in_sel ? g_x : nodes;

    __shared__ float As[16][128];
    __shared__ float Brs[16][64];
    __shared__ float B0s[16][64];

    const int row0 = blockIdx.x * 128;
    const int col0 = blockIdx.y * 64;
    const int tid = threadIdx.x;
    const int tx = tid & 15;       // N direction (x4)
    const int ty = tid >> 4;       // M direction (x8)

    float accr[8][4], acc0[8][4];
#pragma unroll
    for (int i = 0; i < 8; i++)
#pragma unroll
        for (int j = 0; j < 4; j++) { accr[i][j] = 0.f; acc0[i][j] = 0.f; }

    const int r  = tid >> 2;            // 0..63
    const int kq = (tid & 3) << 2;      // 0,4,8,12

    for (int k0 = 0; k0 < DD; k0 += 16) {
        // A tile: 128 x 16, transposed into As[k][m]
#pragma unroll
        for (int it = 0; it < 2; it++) {
            int rr = r + it * 64;
            float4 v = *(const float4*)&X[(size_t)(row0 + rr) * DD + k0 + kq];
            As[kq + 0][rr] = v.x; As[kq + 1][rr] = v.y;
            As[kq + 2][rr] = v.z; As[kq + 3][rr] = v.w;
        }
        // Weight tiles (both), transposed on the fly: Bs[k][n] = W[col0+n][k0+k]
        {
            int n = tid >> 2;           // 0..63
            float4 v = *(const float4*)&Wr[(size_t)(col0 + n) * DD + k0 + kq];
            Brs[kq + 0][n] = v.x; Brs[kq + 1][n] = v.y;
            Brs[kq + 2][n] = v.z; Brs[kq + 3][n] = v.w;
            float4 w = *(const float4*)&W0[(size_t)(col0 + n) * DD + k0 + kq];
            B0s[kq + 0][n] = w.x; B0s[kq + 1][n] = w.y;
            B0s[kq + 2][n] = w.z; B0s[kq + 3][n] = w.w;
        }
        __syncthreads();
#pragma unroll
        for (int k = 0; k < 16; k++) {
            float a[8], bfr[4], bf0[4];
#pragma unroll
            for (int i = 0; i < 8; i++) a[i] = As[k][ty * 8 + i];
#pragma unroll
            for (int j = 0; j < 4; j++) { bfr[j] = Brs[k][tx * 4 + j]; bf0[j] = B0s[k][tx * 4 + j]; }
#pragma unroll
            for (int i = 0; i < 8; i++)
#pragma unroll
                for (int j = 0; j < 4; j++) {
                    accr[i][j] = fmaf(a[i], bfr[j], accr[i][j]);
                    acc0[i][j] = fmaf(a[i], bf0[j], acc0[i][j]);
                }
        }
        __syncthreads();
    }

    const float4 bvr = *(const float4*)&br[col0 + tx * 4];
    const float4 bv0 = *(const float4*)&b0[col0 + tx * 4];
#pragma unroll
    for (int i = 0; i < 8; i++) {
        size_t off = (size_t)(row0 + ty * 8 + i) * DD + col0 + tx * 4;
        float4 o;
        o.x = accr[i][0] + bvr.x; o.y = accr[i][1] + bvr.y;
        o.z = accr[i][2] + bvr.z; o.w = accr[i][3] + bvr.w;
        *(float4*)&g_t[off] = o;
        o.x = acc0[i][0] + bv0.x; o.y = acc0[i][1] + bv0.y;
        o.z = acc0[i][2] + bv0.z; o.w = acc0[i][3] + bv0.w;
        *(float4*)&g_u[off] = o;
    }
}

// ---------------------------------------------------------------------------
// Big batched NN GEMM with fused epilogue:
//   C[b] = adj[b] (2048x2048) @ g_t[b] (2048x256)
//   x_new = relu((C + g_u) / denom);  last layer: out = nodes + x_new
// Tile: BM=128, BN=64, BK=16, 256 threads, 8x4 per thread
// ---------------------------------------------------------------------------
__global__ void __launch_bounds__(256, 4) big_gemm(
    const float* __restrict__ adj, const float* __restrict__ nodes,
    float* __restrict__ out, int last)
{
    const int b = blockIdx.z;
    const float* __restrict__ A  = adj + (size_t)b * NNODE * NNODE;
    const float* __restrict__ Bm = g_t + (size_t)b * NNODE * DD;

    __shared__ float As[16][128];
    __shared__ float Bs[16][64];

    const int row0 = blockIdx.x * 128;
    const int col0 = blockIdx.y * 64;
    const int tid = threadIdx.x;
    const int tx = tid & 15;
    const int ty = tid >> 4;

    float acc[8][4];
#pragma unroll
    for (int i = 0; i < 8; i++)
#pragma unroll
        for (int j = 0; j < 4; j++) acc[i][j] = 0.f;

    const int r  = tid >> 2;
    const int kq = (tid & 3) << 2;
    const int kk = tid >> 4;            // 0..15
    const int nq = (tid & 15) << 2;     // 0..60

    for (int k0 = 0; k0 < NNODE; k0 += 16) {
        // A tile: adj rows, transposed into As[k][m]
#pragma unroll
        for (int it = 0; it < 2; it++) {
            int rr = r + it * 64;
            float4 v = *(const float4*)&A[(size_t)(row0 + rr) * NNODE + k0 + kq];
            As[kq + 0][rr] = v.x; As[kq + 1][rr] = v.y;
            As[kq + 2][rr] = v.z; As[kq + 3][rr] = v.w;
        }
        // B tile: row-major [K, N] slab, direct float4 copy
        {
            float4 v = *(const float4*)&Bm[(size_t)(k0 + kk) * DD + col0 + nq];
            *(float4*)&Bs[kk][nq] = v;
        }
        __syncthreads();
#pragma unroll
        for (int k = 0; k < 16; k++) {
            float a[8], bfr[4];
#pragma unroll
            for (int i = 0; i < 8; i++) a[i] = As[k][ty * 8 + i];
#pragma unroll
            for (int j = 0; j < 4; j++) bfr[j] = Bs[k][tx * 4 + j];
#pragma unroll
            for (int i = 0; i < 8; i++)
#pragma unroll
                for (int j = 0; j < 4; j++) acc[i][j] = fmaf(a[i], bfr[j], acc[i][j]);
        }
        __syncthreads();
    }

#pragma unroll
    for (int i = 0; i < 8; i++) {
        int row = row0 + ty * 8 + i;
        size_t gr = (size_t)b * NNODE + row;
        float inv = 1.0f / g_denom[gr];
        size_t off = gr * DD + col0 + tx * 4;
        float4 u = *(const float4*)&g_u[off];
        float4 o;
        o.x = fmaxf((acc[i][0] + u.x) * inv, 0.f);
        o.y = fmaxf((acc[i][1] + u.y) * inv, 0.f);
        o.z = fmaxf((acc[i][2] + u.z) * inv, 0.f);
        o.w = fmaxf((acc[i][3] + u.w) * inv, 0.f);
        if (last) {
            float4 nd = *(const float4*)&nodes[off];
            o.x += nd.x; o.y += nd.y; o.z += nd.z; o.w += nd.w;
            *(float4*)&out[off] = o;
        } else {
            *(float4*)&g_x[off] = o;
        }
    }
}

// ---------------------------------------------------------------------------
extern "C" void kernel_launch(void* const* d_in, const int* in_sizes, int n_in,
                              void* d_out, int out_size) {
    const float* nodes = (const float*)d_in[0];
    const float* adj   = (const float*)d_in[1];
    const float* W0_w  = (const float*)d_in[2];
    const float* W0_b  = (const float*)d_in[3];
    const float* Wr_w  = (const float*)d_in[4];
    const float* Wr_b  = (const float*)d_in[5];
    float* out = (float*)d_out;

    denom_kernel<<<RR, 256>>>(adj);

    dim3 sgrid(RR / 128, DD / 64);        // 128 x 4 = 512 blocks
    dim3 bgrid(NNODE / 128, DD / 64, BB); // 16 x 4 x 8 = 512 blocks

    for (int l = 0; l < 2; l++) {
        const float* wr = Wr_w + (size_t)l * DD * DD;
        const float* br = Wr_b + (size_t)l * DD;
        const float* w0 = W0_w + (size_t)l * DD * DD;
        const float* b0 = W0_b + (size_t)l * DD;
        dual_gemm<<<sgrid, 256>>>(l, nodes, wr, br, w0, b0); // -> g_t, g_u
        big_gemm<<<bgrid, 256>>>(adj, nodes, out, l == 1);
    }
}

// round 4
// speedup vs baseline: 4.0904x; 4.0904x over previous
#include <cuda_runtime.h>
#include <cstdint>

#define BB 8
#define NNODE 2048
#define DD 256
#define RR (BB*NNODE)   // 16384 total rows

// Scratch (allocation-free rule: device globals)
__device__ float g_x[BB*NNODE*DD];   // current layer activations
__device__ float g_t[BB*NNODE*DD];   // xWr
__device__ float g_u[BB*NNODE*DD];   // xW0
__device__ float g_denom[RR];

// ---------------------------------------------------------------------------
// denom[b,n] = sum_k adj[b,n,k] + 1
// ---------------------------------------------------------------------------
__global__ void denom_kernel(const float* __restrict__ adj) {
    __shared__ float red[8];
    int row = blockIdx.x;
    const float4* a = (const float4*)(adj + (size_t)row * NNODE);
    float s = 0.f;
#pragma unroll
    for (int i = 0; i < 2; i++) {
        float4 v = a[threadIdx.x + i * 256];
        s += (v.x + v.y) + (v.z + v.w);
    }
#pragma unroll
    for (int o = 16; o > 0; o >>= 1) s += __shfl_xor_sync(0xffffffffu, s, o);
    if ((threadIdx.x & 31) == 0) red[threadIdx.x >> 5] = s;
    __syncthreads();
    if (threadIdx.x < 8) {
        s = red[threadIdx.x];
#pragma unroll
        for (int o = 4; o > 0; o >>= 1) s += __shfl_xor_sync(0xffu, s, o);
        if (threadIdx.x == 0) g_denom[row] = s + 1.0f;
    }
}

// ---------------------------------------------------------------------------
// Fused dual NT GEMM (unchanged from passing R2 kernel):
//   g_t[r,m] = sum_d X[r,d]*Wr[m,d] + br[m]
//   g_u[r,m] = sum_d X[r,d]*W0[m,d] + b0[m]
// ---------------------------------------------------------------------------
__global__ void __launch_bounds__(256, 2) dual_gemm(
    int in_sel, const float* __restrict__ nodes,
    const float* __restrict__ Wr, const float* __restrict__ br,
    const float* __restrict__ W0, const float* __restrict__ b0)
{
    const float* __restrict__ X = in_sel ? g_x : nodes;

    __shared__ float As[16][128];
    __shared__ float Brs[16][64];
    __shared__ float B0s[16][64];

    const int row0 = blockIdx.x * 128;
    const int col0 = blockIdx.y * 64;
    const int tid = threadIdx.x;
    const int tx = tid & 15;
    const int ty = tid >> 4;

    float accr[8][4], acc0[8][4];
#pragma unroll
    for (int i = 0; i < 8; i++)
#pragma unroll
        for (int j = 0; j < 4; j++) { accr[i][j] = 0.f; acc0[i][j] = 0.f; }

    const int r  = tid >> 2;
    const int kq = (tid & 3) << 2;

    for (int k0 = 0; k0 < DD; k0 += 16) {
#pragma unroll
        for (int it = 0; it < 2; it++) {
            int rr = r + it * 64;
            float4 v = *(const float4*)&X[(size_t)(row0 + rr) * DD + k0 + kq];
            As[kq + 0][rr] = v.x; As[kq + 1][rr] = v.y;
            As[kq + 2][rr] = v.z; As[kq + 3][rr] = v.w;
        }
        {
            int n = tid >> 2;
            float4 v = *(const float4*)&Wr[(size_t)(col0 + n) * DD + k0 + kq];
            Brs[kq + 0][n] = v.x; Brs[kq + 1][n] = v.y;
            Brs[kq + 2][n] = v.z; Brs[kq + 3][n] = v.w;
            float4 w = *(const float4*)&W0[(size_t)(col0 + n) * DD + k0 + kq];
            B0s[kq + 0][n] = w.x; B0s[kq + 1][n] = w.y;
            B0s[kq + 2][n] = w.z; B0s[kq + 3][n] = w.w;
        }
        __syncthreads();
#pragma unroll
        for (int k = 0; k < 16; k++) {
            float a[8], bfr[4], bf0[4];
#pragma unroll
            for (int i = 0; i < 8; i++) a[i] = As[k][ty * 8 + i];
#pragma unroll
            for (int j = 0; j < 4; j++) { bfr[j] = Brs[k][tx * 4 + j]; bf0[j] = B0s[k][tx * 4 + j]; }
#pragma unroll
            for (int i = 0; i < 8; i++)
#pragma unroll
                for (int j = 0; j < 4; j++) {
                    accr[i][j] = fmaf(a[i], bfr[j], accr[i][j]);
                    acc0[i][j] = fmaf(a[i], bf0[j], acc0[i][j]);
                }
        }
        __syncthreads();
    }

    const float4 bvr = *(const float4*)&br[col0 + tx * 4];
    const float4 bv0 = *(const float4*)&b0[col0 + tx * 4];
#pragma unroll
    for (int i = 0; i < 8; i++) {
        size_t off = (size_t)(row0 + ty * 8 + i) * DD + col0 + tx * 4;
        float4 o;
        o.x = accr[i][0] + bvr.x; o.y = accr[i][1] + bvr.y;
        o.z = accr[i][2] + bvr.z; o.w = accr[i][3] + bvr.w;
        *(float4*)&g_t[off] = o;
        o.x = acc0[i][0] + bv0.x; o.y = acc0[i][1] + bv0.y;
        o.z = acc0[i][2] + bv0.z; o.w = acc0[i][3] + bv0.w;
        *(float4*)&g_u[off] = o;
    }
}

// ---------------------------------------------------------------------------
// Tensor-core big GEMM via legacy mma.sync tf32 (sm_80 path, works on sm_103):
//   C[b][row][n] = sum_k adj[b][row][k] * g_t[b][k][n]
// CTA tile 128x128x32, 8 warps of 64x32, double-buffered cp.async.
// fp32 inputs fed raw to tf32 mma (HW truncates mantissa; error ~5e-4 on the
// aggregate, diluted by /denom (~1025) and the residual -> ~1e-5 output err.
// ---------------------------------------------------------------------------
#define KT 32
#define NT_ITERS (NNODE / KT)        // 64
#define ASTR 36                      // A smem word stride (conflict-free frags)
#define BSTR 136                     // B smem word stride
#define A_WORDS (128 * ASTR)         // 4608
#define B_WORDS (KT * BSTR)          // 4352
#define SMEM_MMA ((2 * A_WORDS + 2 * B_WORDS) * 4)   // 71680 bytes

__device__ __forceinline__ uint32_t smem_u32(const void* p) {
    uint32_t a;
    asm("{ .reg .u64 t; cvta.to.shared.u64 t, %1; cvt.u32.u64 %0, t; }" : "=r"(a) : "l"(p));
    return a;
}
__device__ __forceinline__ void cp16(uint32_t saddr, const void* gaddr) {
    asm volatile("cp.async.ca.shared.global [%0], [%1], 16;" :: "r"(saddr), "l"(gaddr) : "memory");
}

__global__ void __launch_bounds__(256, 2) big_gemm_mma(
    const float* __restrict__ adj, const float* __restrict__ nodes,
    float* __restrict__ out, int last)
{
    extern __shared__ float smf[];
    const int tid = threadIdx.x;
    const int lane = tid & 31, wid = tid >> 5;
    const int wm = wid >> 2, wn = wid & 3;          // warp tile: 64(M) x 32(N)
    const int mt = blockIdx.x, nt = blockIdx.y, b = blockIdx.z;

    const float* A  = adj + (size_t)b * NNODE * NNODE + (size_t)mt * 128 * NNODE;
    const float* Bg = g_t + (size_t)b * NNODE * DD + nt * 128;

    float* AsBase = smf;                    // [2][A_WORDS]
    float* BsBase = smf + 2 * A_WORDS;      // [2][B_WORDS]
    const uint32_t sA = smem_u32(AsBase);
    const uint32_t sB = smem_u32(BsBase);

    float acc[4][4][4];
#pragma unroll
    for (int mi = 0; mi < 4; mi++)
#pragma unroll
        for (int ni = 0; ni < 4; ni++)
#pragma unroll
            for (int q = 0; q < 4; q++) acc[mi][ni][q] = 0.f;

    // loader coordinates (4 float4 each for A and B per thread)
    int la_row[4], la_kq[4], lb_k[4], lb_n4[4];
#pragma unroll
    for (int i = 0; i < 4; i++) {
        int idx = tid + i * 256;
        la_row[i] = idx >> 3;  la_kq[i] = (idx & 7) << 2;   // A: 128 rows x 8 f4
        lb_k[i]   = idx >> 5;  lb_n4[i] = (idx & 31) << 2;  // B: 32 k x 32 f4
    }

    auto issue_tile = [&](int t, int p) {
        int k0 = t * KT;
        uint32_t a0 = sA + (uint32_t)p * A_WORDS * 4;
        uint32_t b0 = sB + (uint32_t)p * B_WORDS * 4;
#pragma unroll
        for (int i = 0; i < 4; i++)
            cp16(a0 + (la_row[i] * ASTR + la_kq[i]) * 4,
                 A + (size_t)la_row[i] * NNODE + k0 + la_kq[i]);
#pragma unroll
        for (int i = 0; i < 4; i++)
            cp16(b0 + (lb_k[i] * BSTR + lb_n4[i]) * 4,
                 Bg + (size_t)(k0 + lb_k[i]) * DD + lb_n4[i]);
        asm volatile("cp.async.commit_group;" ::: "memory");
    };

    issue_tile(0, 0);

    const int g = lane >> 2, tg = lane & 3;

    for (int t = 0; t < NT_ITERS; t++) {
        int p = t & 1;
        if (t + 1 < NT_ITERS) {
            issue_tile(t + 1, (t + 1) & 1);
            asm volatile("cp.async.wait_group 1;" ::: "memory");
        } else {
            asm volatile("cp.async.wait_group 0;" ::: "memory");
        }
        __syncthreads();

        const float* Asb = AsBase + p * A_WORDS;
        const float* Bsb = BsBase + p * B_WORDS;
#pragma unroll
        for (int ks = 0; ks < 4; ks++) {
            uint32_t afr[4][4], bfr[4][2];
#pragma unroll
            for (int mi = 0; mi < 4; mi++) {
                int rb = wm * 64 + mi * 16;
                int kc = ks * 8 + tg;
                afr[mi][0] = __float_as_uint(Asb[(rb + g)      * ASTR + kc]);
                afr[mi][1] = __float_as_uint(Asb[(rb + 8 + g)  * ASTR + kc]);
                afr[mi][2] = __float_as_uint(Asb[(rb + g)      * ASTR + kc + 4]);
                afr[mi][3] = __float_as_uint(Asb[(rb + 8 + g)  * ASTR + kc + 4]);
            }
#pragma unroll
            for (int ni = 0; ni < 4; ni++) {
                int nb = wn * 32 + ni * 8 + g;
                bfr[ni][0] = __float_as_uint(Bsb[(ks * 8 + tg)     * BSTR + nb]);
                bfr[ni][1] = __float_as_uint(Bsb[(ks * 8 + tg + 4) * BSTR + nb]);
            }
#pragma unroll
            for (int mi = 0; mi < 4; mi++)
#pragma unroll
                for (int ni = 0; ni < 4; ni++) {
                    asm volatile(
                        "mma.sync.aligned.m16n8k8.row.col.f32.tf32.tf32.f32 "
                        "{%0,%1,%2,%3}, {%4,%5,%6,%7}, {%8,%9}, {%0,%1,%2,%3};"
                        : "+f"(acc[mi][ni][0]), "+f"(acc[mi][ni][1]),
                          "+f"(acc[mi][ni][2]), "+f"(acc[mi][ni][3])
                        : "r"(afr[mi][0]), "r"(afr[mi][1]), "r"(afr[mi][2]), "r"(afr[mi][3]),
                          "r"(bfr[ni][0]), "r"(bfr[ni][1]));
                }
        }
        __syncthreads();
    }

    // Epilogue: relu((C + u) / denom) (+ nodes on last layer)
#pragma unroll
    for (int mi = 0; mi < 4; mi++) {
        int rl1 = wm * 64 + mi * 16 + g;
        int rl2 = rl1 + 8;
        int row1 = mt * 128 + rl1, row2 = mt * 128 + rl2;
        size_t gr1 = (size_t)b * NNODE + row1, gr2 = (size_t)b * NNODE + row2;
        float inv1 = 1.0f / g_denom[gr1];
        float inv2 = 1.0f / g_denom[gr2];
#pragma unroll
        for (int ni = 0; ni < 4; ni++) {
            int col = nt * 128 + wn * 32 + ni * 8 + tg * 2;
            size_t o1 = gr1 * DD + col, o2 = gr2 * DD + col;
            float2 u1 = *(const float2*)&g_u[o1];
            float2 u2 = *(const float2*)&g_u[o2];
            float2 v1, v2;
            v1.x = fmaxf((acc[mi][ni][0] + u1.x) * inv1, 0.f);
            v1.y = fmaxf((acc[mi][ni][1] + u1.y) * inv1, 0.f);
            v2.x = fmaxf((acc[mi][ni][2] + u2.x) * inv2, 0.f);
            v2.y = fmaxf((acc[mi][ni][3] + u2.y) * inv2, 0.f);
            if (last) {
                float2 n1 = *(const float2*)&nodes[o1];
                float2 n2 = *(const float2*)&nodes[o2];
                v1.x += n1.x; v1.y += n1.y; v2.x += n2.x; v2.y += n2.y;
                *(float2*)&out[o1] = v1;
                *(float2*)&out[o2] = v2;
            } else {
                *(float2*)&g_x[o1] = v1;
                *(float2*)&g_x[o2] = v2;
            }
        }
    }
}

// ---------------------------------------------------------------------------
extern "C" void kernel_launch(void* const* d_in, const int* in_sizes, int n_in,
                              void* d_out, int out_size) {
    const float* nodes = (const float*)d_in[0];
    const float* adj   = (const float*)d_in[1];
    const float* W0_w  = (const float*)d_in[2];
    const float* W0_b  = (const float*)d_in[3];
    const float* Wr_w  = (const float*)d_in[4];
    const float* Wr_b  = (const float*)d_in[5];
    float* out = (float*)d_out;

    static int cfg_done = 0;
    if (!cfg_done) {
        cudaFuncSetAttribute(big_gemm_mma, cudaFuncAttributeMaxDynamicSharedMemorySize, SMEM_MMA);
        cfg_done = 1;
    }

    denom_kernel<<<RR, 256>>>(adj);

    dim3 sgrid(RR / 128, DD / 64);     // 128 x 4
    dim3 bgrid(NNODE / 128, DD / 128, BB);  // 16 x 2 x 8 = 256 CTAs

    for (int l = 0; l < 2; l++) {
        const float* wr = Wr_w + (size_t)l * DD * DD;
        const float* br = Wr_b + (size_t)l * DD;
        const float* w0 = W0_w + (size_t)l * DD * DD;
        const float* b0 = W0_b + (size_t)l * DD;
        dual_gemm<<<sgrid, 256>>>(l, nodes, wr, br, w0, b0);   // -> g_t, g_u
        big_gemm_mma<<<bgrid, 256, SMEM_MMA>>>(adj, nodes, out, l == 1);
    }
}

// round 6
// speedup vs baseline: 6.0885x; 1.4885x over previous
#include <cuda_runtime.h>
#include <cstdint>

#define BB 8
#define NNODE 2048
#define DD 256
#define RR (BB*NNODE)   // 16384 total rows

// Scratch (allocation-free rule: device globals)
__device__ float g_x[BB*NNODE*DD];   // current layer activations
__device__ float g_t[BB*NNODE*DD];   // xWr
__device__ float g_u[BB*NNODE*DD];   // xW0
__device__ float g_denom[RR];

__device__ __forceinline__ uint32_t smem_u32(const void* p) {
    uint32_t a;
    asm("{ .reg .u64 t; cvta.to.shared.u64 t, %1; cvt.u32.u64 %0, t; }" : "=r"(a) : "l"(p));
    return a;
}
__device__ __forceinline__ void cp16(uint32_t saddr, const void* gaddr) {
    asm volatile("cp.async.ca.shared.global [%0], [%1], 16;" :: "r"(saddr), "l"(gaddr) : "memory");
}

// ---------------------------------------------------------------------------
// denom[b,n] = sum_k adj[b,n,k] + 1
// ---------------------------------------------------------------------------
__global__ void denom_kernel(const float* __restrict__ adj) {
    __shared__ float red[8];
    int row = blockIdx.x;
    const float4* a = (const float4*)(adj + (size_t)row * NNODE);
    float s = 0.f;
#pragma unroll
    for (int i = 0; i < 2; i++) {
        float4 v = a[threadIdx.x + i * 256];
        s += (v.x + v.y) + (v.z + v.w);
    }
#pragma unroll
    for (int o = 16; o > 0; o >>= 1) s += __shfl_xor_sync(0xffffffffu, s, o);
    if ((threadIdx.x & 31) == 0) red[threadIdx.x >> 5] = s;
    __syncthreads();
    if (threadIdx.x < 8) {
        s = red[threadIdx.x];
#pragma unroll
        for (int o = 4; o > 0; o >>= 1) s += __shfl_xor_sync(0xffu, s, o);
        if (threadIdx.x == 0) g_denom[row] = s + 1.0f;
    }
}

// ---------------------------------------------------------------------------
// Small GEMM via tf32 mma.sync:
//   nt<2: g_t[r, nt*128 + n] = sum_d X[r,d]*Wr[nt*128+n, d] + br[...]
//   nt>=2: same with W0/b0 -> g_u
// CTA 128x128, K=256 in 8 chunks of 32, double-buffered cp.async.
// Both A (X) and B (W) are k-contiguous row-major -> direct cp.async, no
// transpose. Smem stride 36 words (==4 mod 32) => conflict-free frag loads.
// ---------------------------------------------------------------------------
#define SSTR 36
#define S_WORDS (128 * SSTR)                    // 4608 per operand per stage
#define SMEM_SMALL (4 * S_WORDS * 4)            // 73728 bytes

__global__ void __launch_bounds__(256, 2) small_mma(
    int in_sel, const float* __restrict__ nodes,
    const float* __restrict__ Wr, const float* __restrict__ br,
    const float* __restrict__ W0, const float* __restrict__ b0)
{
    extern __shared__ float smf[];
    const float* __restrict__ X = in_sel ? g_x : nodes;

    const int tid = threadIdx.x;
    const int lane = tid & 31, wid = tid >> 5;
    const int wm = wid >> 2, wn = wid & 3;      // warp tile 64(M) x 32(N)
    const int mt = blockIdx.x, nt = blockIdx.y;

    const int row0 = mt * 128;
    const int wsel = nt >> 1;                   // 0 = Wr->g_t, 1 = W0->g_u
    const int col0 = (nt & 1) * 128;
    const float* Wg = (wsel ? W0 : Wr) + (size_t)col0 * DD;
    const float* bias = (wsel ? b0 : br) + col0;
    float* C = wsel ? g_u : g_t;

    float* AsBase = smf;                 // [2][S_WORDS]
    float* BsBase = smf + 2 * S_WORDS;   // [2][S_WORDS]
    const uint32_t sA = smem_u32(AsBase);
    const uint32_t sB = smem_u32(BsBase);

    float acc[4][4][4];
#pragma unroll
    for (int mi = 0; mi < 4; mi++)
#pragma unroll
        for (int ni = 0; ni < 4; ni++)
#pragma unroll
            for (int q = 0; q < 4; q++) acc[mi][ni][q] = 0.f;

    // loaders: 128 rows x 8 float4 (32 floats of K) for each operand
    int lrow[4], lkq[4];
#pragma unroll
    for (int i = 0; i < 4; i++) {
        int idx = tid + i * 256;
        lrow[i] = idx >> 3;  lkq[i] = (idx & 7) << 2;
    }

    auto issue_tile = [&](int k0, int p) {
        uint32_t a0 = sA + (uint32_t)p * S_WORDS * 4;
        uint32_t b0a = sB + (uint32_t)p * S_WORDS * 4;
#pragma unroll
        for (int i = 0; i < 4; i++)
            cp16(a0 + (lrow[i] * SSTR + lkq[i]) * 4,
                 X + (size_t)(row0 + lrow[i]) * DD + k0 + lkq[i]);
#pragma unroll
        for (int i = 0; i < 4; i++)
            cp16(b0a + (lrow[i] * SSTR + lkq[i]) * 4,
                 Wg + (size_t)lrow[i] * DD + k0 + lkq[i]);
        asm volatile("cp.async.commit_group;" ::: "memory");
    };

    issue_tile(0, 0);

    const int g = lane >> 2, tg = lane & 3;
    const int NKI = DD / 32;   // 8

    for (int t = 0; t < NKI; t++) {
        int p = t & 1;
        if (t + 1 < NKI) {
            issue_tile((t + 1) * 32, (t + 1) & 1);
            asm volatile("cp.async.wait_group 1;" ::: "memory");
        } else {
            asm volatile("cp.async.wait_group 0;" ::: "memory");
        }
        __syncthreads();

        const float* Asb = AsBase + p * S_WORDS;
        const float* Bsb = BsBase + p * S_WORDS;
#pragma unroll
        for (int ks = 0; ks < 4; ks++) {
            uint32_t afr[4][4], bfr[4][2];
#pragma unroll
            for (int mi = 0; mi < 4; mi++) {
                int rb = wm * 64 + mi * 16;
                int kc = ks * 8 + tg;
                afr[mi][0] = __float_as_uint(Asb[(rb + g)     * SSTR + kc]);
                afr[mi][1] = __float_as_uint(Asb[(rb + 8 + g) * SSTR + kc]);
                afr[mi][2] = __float_as_uint(Asb[(rb + g)     * SSTR + kc + 4]);
                afr[mi][3] = __float_as_uint(Asb[(rb + 8 + g) * SSTR + kc + 4]);
            }
#pragma unroll
            for (int ni = 0; ni < 4; ni++) {
                int nb = wn * 32 + ni * 8 + g;
                bfr[ni][0] = __float_as_uint(Bsb[nb * SSTR + ks * 8 + tg]);
                bfr[ni][1] = __float_as_uint(Bsb[nb * SSTR + ks * 8 + tg + 4]);
            }
#pragma unroll
            for (int mi = 0; mi < 4; mi++)
#pragma unroll
                for (int ni = 0; ni < 4; ni++) {
                    asm volatile(
                        "mma.sync.aligned.m16n8k8.row.col.f32.tf32.tf32.f32 "
                        "{%0,%1,%2,%3}, {%4,%5,%6,%7}, {%8,%9}, {%0,%1,%2,%3};"
                        : "+f"(acc[mi][ni][0]), "+f"(acc[mi][ni][1]),
                          "+f"(acc[mi][ni][2]), "+f"(acc[mi][ni][3])
                        : "r"(afr[mi][0]), "r"(afr[mi][1]), "r"(afr[mi][2]), "r"(afr[mi][3]),
                          "r"(bfr[ni][0]), "r"(bfr[ni][1]));
                }
        }
        __syncthreads();
    }

    // Epilogue: + bias, store
#pragma unroll
    for (int mi = 0; mi < 4; mi++) {
        int rl1 = wm * 64 + mi * 16 + g;
        int rl2 = rl1 + 8;
        size_t r1 = (size_t)(row0 + rl1) * DD, r2 = (size_t)(row0 + rl2) * DD;
#pragma unroll
        for (int ni = 0; ni < 4; ni++) {
            int nc = wn * 32 + ni * 8 + tg * 2;
            int col = col0 + nc;
            float2 bv = *(const float2*)&bias[nc];
            float2 v1, v2;
            v1.x = acc[mi][ni][0] + bv.x; v1.y = acc[mi][ni][1] + bv.y;
            v2.x = acc[mi][ni][2] + bv.x; v2.y = acc[mi][ni][3] + bv.y;
            *(float2*)&C[r1 + col] = v1;
            *(float2*)&C[r2 + col] = v2;
        }
    }
}

// ---------------------------------------------------------------------------
// Tensor-core big GEMM via mma.sync tf32 (unchanged from R4 passing kernel)
// ---------------------------------------------------------------------------
#define KT 32
#define NT_ITERS (NNODE / KT)        // 64
#define ASTR 36
#define BSTR 136
#define A_WORDS (128 * ASTR)
#define B_WORDS (KT * BSTR)
#define SMEM_MMA ((2 * A_WORDS + 2 * B_WORDS) * 4)   // 71680 bytes

__global__ void __launch_bounds__(256, 2) big_gemm_mma(
    const float* __restrict__ adj, const float* __restrict__ nodes,
    float* __restrict__ out, int last)
{
    extern __shared__ float smf[];
    const int tid = threadIdx.x;
    const int lane = tid & 31, wid = tid >> 5;
    const int wm = wid >> 2, wn = wid & 3;
    const int mt = blockIdx.x, nt = blockIdx.y, b = blockIdx.z;

    const float* A  = adj + (size_t)b * NNODE * NNODE + (size_t)mt * 128 * NNODE;
    const float* Bg = g_t + (size_t)b * NNODE * DD + nt * 128;

    float* AsBase = smf;
    float* BsBase = smf + 2 * A_WORDS;
    const uint32_t sA = smem_u32(AsBase);
    const uint32_t sB = smem_u32(BsBase);

    float acc[4][4][4];
#pragma unroll
    for (int mi = 0; mi < 4; mi++)
#pragma unroll
        for (int ni = 0; ni < 4; ni++)
#pragma unroll
            for (int q = 0; q < 4; q++) acc[mi][ni][q] = 0.f;

    int la_row[4], la_kq[4], lb_k[4], lb_n4[4];
#pragma unroll
    for (int i = 0; i < 4; i++) {
        int idx = tid + i * 256;
        la_row[i] = idx >> 3;  la_kq[i] = (idx & 7) << 2;
        lb_k[i]   = idx >> 5;  lb_n4[i] = (idx & 31) << 2;
    }

    auto issue_tile = [&](int t, int p) {
        int k0 = t * KT;
        uint32_t a0 = sA + (uint32_t)p * A_WORDS * 4;
        uint32_t b0 = sB + (uint32_t)p * B_WORDS * 4;
#pragma unroll
        for (int i = 0; i < 4; i++)
            cp16(a0 + (la_row[i] * ASTR + la_kq[i]) * 4,
                 A + (size_t)la_row[i] * NNODE + k0 + la_kq[i]);
#pragma unroll
        for (int i = 0; i < 4; i++)
            cp16(b0 + (lb_k[i] * BSTR + lb_n4[i]) * 4,
                 Bg + (size_t)(k0 + lb_k[i]) * DD + lb_n4[i]);
        asm volatile("cp.async.commit_group;" ::: "memory");
    };

    issue_tile(0, 0);

    const int g = lane >> 2, tg = lane & 3;

    for (int t = 0; t < NT_ITERS; t++) {
        int p = t & 1;
        if (t + 1 < NT_ITERS) {
            issue_tile(t + 1, (t + 1) & 1);
            asm volatile("cp.async.wait_group 1;" ::: "memory");
        } else {
            asm volatile("cp.async.wait_group 0;" ::: "memory");
        }
        __syncthreads();

        const float* Asb = AsBase + p * A_WORDS;
        const float* Bsb = BsBase + p * B_WORDS;
#pragma unroll
        for (int ks = 0; ks < 4; ks++) {
            uint32_t afr[4][4], bfr[4][2];
#pragma unroll
            for (int mi = 0; mi < 4; mi++) {
                int rb = wm * 64 + mi * 16;
                int kc = ks * 8 + tg;
                afr[mi][0] = __float_as_uint(Asb[(rb + g)      * ASTR + kc]);
                afr[mi][1] = __float_as_uint(Asb[(rb + 8 + g)  * ASTR + kc]);
                afr[mi][2] = __float_as_uint(Asb[(rb + g)      * ASTR + kc + 4]);
                afr[mi][3] = __float_as_uint(Asb[(rb + 8 + g)  * ASTR + kc + 4]);
            }
#pragma unroll
            for (int ni = 0; ni < 4; ni++) {
                int nb = wn * 32 + ni * 8 + g;
                bfr[ni][0] = __float_as_uint(Bsb[(ks * 8 + tg)     * BSTR + nb]);
                bfr[ni][1] = __float_as_uint(Bsb[(ks * 8 + tg + 4) * BSTR + nb]);
            }
#pragma unroll
            for (int mi = 0; mi < 4; mi++)
#pragma unroll
                for (int ni = 0; ni < 4; ni++) {
                    asm volatile(
                        "mma.sync.aligned.m16n8k8.row.col.f32.tf32.tf32.f32 "
                        "{%0,%1,%2,%3}, {%4,%5,%6,%7}, {%8,%9}, {%0,%1,%2,%3};"
                        : "+f"(acc[mi][ni][0]), "+f"(acc[mi][ni][1]),
                          "+f"(acc[mi][ni][2]), "+f"(acc[mi][ni][3])
                        : "r"(afr[mi][0]), "r"(afr[mi][1]), "r"(afr[mi][2]), "r"(afr[mi][3]),
                          "r"(bfr[ni][0]), "r"(bfr[ni][1]));
                }
        }
        __syncthreads();
    }

#pragma unroll
    for (int mi = 0; mi < 4; mi++) {
        int rl1 = wm * 64 + mi * 16 + g;
        int rl2 = rl1 + 8;
        int row1 = mt * 128 + rl1, row2 = mt * 128 + rl2;
        size_t gr1 = (size_t)b * NNODE + row1, gr2 = (size_t)b * NNODE + row2;
        float inv1 = 1.0f / g_denom[gr1];
        float inv2 = 1.0f / g_denom[gr2];
#pragma unroll
        for (int ni = 0; ni < 4; ni++) {
            int col = nt * 128 + wn * 32 + ni * 8 + tg * 2;
            size_t o1 = gr1 * DD + col, o2 = gr2 * DD + col;
            float2 u1 = *(const float2*)&g_u[o1];
            float2 u2 = *(const float2*)&g_u[o2];
            float2 v1, v2;
            v1.x = fmaxf((acc[mi][ni][0] + u1.x) * inv1, 0.f);
            v1.y = fmaxf((acc[mi][ni][1] + u1.y) * inv1, 0.f);
            v2.x = fmaxf((acc[mi][ni][2] + u2.x) * inv2, 0.f);
            v2.y = fmaxf((acc[mi][ni][3] + u2.y) * inv2, 0.f);
            if (last) {
                float2 n1 = *(const float2*)&nodes[o1];
                float2 n2 = *(const float2*)&nodes[o2];
                v1.x += n1.x; v1.y += n1.y; v2.x += n2.x; v2.y += n2.y;
                *(float2*)&out[o1] = v1;
                *(float2*)&out[o2] = v2;
            } else {
                *(float2*)&g_x[o1] = v1;
                *(float2*)&g_x[o2] = v2;
            }
        }
    }
}

// ---------------------------------------------------------------------------
extern "C" void kernel_launch(void* const* d_in, const int* in_sizes, int n_in,
                              void* d_out, int out_size) {
    const float* nodes = (const float*)d_in[0];
    const float* adj   = (const float*)d_in[1];
    const float* W0_w  = (const float*)d_in[2];
    const float* W0_b  = (const float*)d_in[3];
    const float* Wr_w  = (const float*)d_in[4];
    const float* Wr_b  = (const float*)d_in[5];
    float* out = (float*)d_out;

    static int cfg_done = 0;
    if (!cfg_done) {
        cudaFuncSetAttribute(big_gemm_mma, cudaFuncAttributeMaxDynamicSharedMemorySize, SMEM_MMA);
        cudaFuncSetAttribute(small_mma,    cudaFuncAttributeMaxDynamicSharedMemorySize, SMEM_SMALL);
        cfg_done = 1;
    }

    denom_kernel<<<RR, 256>>>(adj);

    dim3 sgrid(RR / 128, 4);                 // 128 x 4 = 512 CTAs
    dim3 bgrid(NNODE / 128, DD / 128, BB);   // 16 x 2 x 8 = 256 CTAs

    for (int l = 0; l < 2; l++) {
        const float* wr = Wr_w + (size_t)l * DD * DD;
        const float* br = Wr_b + (size_t)l * DD;
        const float* w0 = W0_w + (size_t)l * DD * DD;
        const float* b0 = W0_b + (size_t)l * DD;
        small_mma<<<sgrid, 256, SMEM_SMALL>>>(l, nodes, wr, br, w0, b0);  // -> g_t, g_u
        big_gemm_mma<<<bgrid, 256, SMEM_MMA>>>(adj, nodes, out, l == 1);
    }
}

// round 10
// speedup vs baseline: 8.7614x; 1.4390x over previous
#include <cuda_runtime.h>
#include <cuda_bf16.h>
#include <cstdint>

#define BB 8
#define NNODE 2048
#define DD 256
#define RR (BB*NNODE)   // 16384 total rows

// Scratch (allocation-free rule: device globals)
__device__ float g_x[BB*NNODE*DD];              // current layer activations (fp32)
__device__ float g_u[BB*NNODE*DD];              // xW0 (fp32)
__device__ float g_denom[RR];
__device__ __nv_bfloat16 g_adjh[(size_t)BB*NNODE*NNODE];  // adj in bf16
__device__ __nv_bfloat16 g_thT[(size_t)BB*DD*NNODE];      // xWr bf16 TRANSPOSED [b][m][r]

__device__ __forceinline__ uint32_t smem_u32(const void* p) {
    uint32_t a;
    asm("{ .reg .u64 t; cvta.to.shared.u64 t, %1; cvt.u32.u64 %0, t; }" : "=r"(a) : "l"(p));
    return a;
}
__device__ __forceinline__ void cp16(uint32_t saddr, const void* gaddr) {
    asm volatile("cp.async.ca.shared.global [%0], [%1], 16;" :: "r"(saddr), "l"(gaddr) : "memory");
}

// ---------------------------------------------------------------------------
// denom[b,n] = sum_k adj[b,n,k] + 1 ; fused adj -> bf16 conversion
// ---------------------------------------------------------------------------
__global__ void denom_kernel(const float* __restrict__ adj) {
    __shared__ float red[8];
    int row = blockIdx.x;
    const float4* a = (const float4*)(adj + (size_t)row * NNODE);
    uint2* ah = (uint2*)(g_adjh + (size_t)row * NNODE);
    float s = 0.f;
#pragma unroll
    for (int i = 0; i < 2; i++) {
        int f = threadIdx.x + i * 256;
        float4 v = a[f];
        s += (v.x + v.y) + (v.z + v.w);
        __nv_bfloat162 lo = __float22bfloat162_rn(make_float2(v.x, v.y));
        __nv_bfloat162 hi = __float22bfloat162_rn(make_float2(v.z, v.w));
        uint2 pk;
        pk.x = *(uint32_t*)&lo;  pk.y = *(uint32_t*)&hi;
        ah[f] = pk;
    }
#pragma unroll
    for (int o = 16; o > 0; o >>= 1) s += __shfl_xor_sync(0xffffffffu, s, o);
    if ((threadIdx.x & 31) == 0) red[threadIdx.x >> 5] = s;
    __syncthreads();
    if (threadIdx.x < 8) {
        s = red[threadIdx.x];
#pragma unroll
        for (int o = 4; o > 0; o >>= 1) s += __shfl_xor_sync(0xffu, s, o);
        if (threadIdx.x == 0) g_denom[row] = s + 1.0f;
    }
}

// ---------------------------------------------------------------------------
// Small GEMM via tf32 mma.sync:
//   nt<2:  xWr tile -> g_thT (bf16, transposed [m][r]) via smem-staged transpose
//   nt>=2: xW0 tile -> g_u (fp32, row-major)
// CTA 128x128, K=256, double-buffered cp.async, stride 36 words conflict-free.
// ---------------------------------------------------------------------------
#define SSTR 36
#define S_WORDS (128 * SSTR)                    // 4608 per operand per stage
#define SMEM_SMALL (4 * S_WORDS * 4)            // 73728 bytes

__global__ void __launch_bounds__(256, 2) small_mma(
    int in_sel, const float* __restrict__ nodes,
    const float* __restrict__ Wr, const float* __restrict__ br,
    const float* __restrict__ W0, const float* __restrict__ b0)
{
    extern __shared__ float smf[];
    const float* __restrict__ X = in_sel ? g_x : nodes;

    const int tid = threadIdx.x;
    const int lane = tid & 31, wid = tid >> 5;
    const int wm = wid >> 2, wn = wid & 3;      // warp tile 64(M) x 32(N)
    const int mt = blockIdx.x, nt = blockIdx.y;

    const int row0 = mt * 128;
    const int wsel = nt >> 1;                   // 0 = Wr->g_thT, 1 = W0->g_u
    const int col0 = (nt & 1) * 128;
    const float* Wg = (wsel ? W0 : Wr) + (size_t)col0 * DD;
    const float* bias = (wsel ? b0 : br) + col0;

    float* AsBase = smf;                 // [2][S_WORDS]
    float* BsBase = smf + 2 * S_WORDS;   // [2][S_WORDS]
    const uint32_t sA = smem_u32(AsBase);
    const uint32_t sB = smem_u32(BsBase);

    float acc[4][4][4];
#pragma unroll
    for (int mi = 0; mi < 4; mi++)
#pragma unroll
        for (int ni = 0; ni < 4; ni++)
#pragma unroll
            for (int q = 0; q < 4; q++) acc[mi][ni][q] = 0.f;

    int lrow[4], lkq[4];
#pragma unroll
    for (int i = 0; i < 4; i++) {
        int idx = tid + i * 256;
        lrow[i] = idx >> 3;  lkq[i] = (idx & 7) << 2;
    }

    auto issue_tile = [&](int k0, int p) {
        uint32_t a0 = sA + (uint32_t)p * S_WORDS * 4;
        uint32_t b0a = sB + (uint32_t)p * S_WORDS * 4;
#pragma unroll
        for (int i = 0; i < 4; i++)
            cp16(a0 + (lrow[i] * SSTR + lkq[i]) * 4,
                 X + (size_t)(row0 + lrow[i]) * DD + k0 + lkq[i]);
#pragma unroll
        for (int i = 0; i < 4; i++)
            cp16(b0a + (lrow[i] * SSTR + lkq[i]) * 4,
                 Wg + (size_t)lrow[i] * DD + k0 + lkq[i]);
        asm volatile("cp.async.commit_group;" ::: "memory");
    };

    issue_tile(0, 0);

    const int g = lane >> 2, tg = lane & 3;
    const int NKI = DD / 32;   // 8

    for (int t = 0; t < NKI; t++) {
        int p = t & 1;
        if (t + 1 < NKI) {
            issue_tile((t + 1) * 32, (t + 1) & 1);
            asm volatile("cp.async.wait_group 1;" ::: "memory");
        } else {
            asm volatile("cp.async.wait_group 0;" ::: "memory");
        }
        __syncthreads();

        const float* Asb = AsBase + p * S_WORDS;
        const float* Bsb = BsBase + p * S_WORDS;
#pragma unroll
        for (int ks = 0; ks < 4; ks++) {
            uint32_t afr[4][4], bfr[4][2];
#pragma unroll
            for (int mi = 0; mi < 4; mi++) {
                int rb = wm * 64 + mi * 16;
                int kc = ks * 8 + tg;
                afr[mi][0] = __float_as_uint(Asb[(rb + g)     * SSTR + kc]);
                afr[mi][1] = __float_as_uint(Asb[(rb + 8 + g) * SSTR + kc]);
                afr[mi][2] = __float_as_uint(Asb[(rb + g)     * SSTR + kc + 4]);
                afr[mi][3] = __float_as_uint(Asb[(rb + 8 + g) * SSTR + kc + 4]);
            }
#pragma unroll
            for (int ni = 0; ni < 4; ni++) {
                int nb = wn * 32 + ni * 8 + g;
                bfr[ni][0] = __float_as_uint(Bsb[nb * SSTR + ks * 8 + tg]);
                bfr[ni][1] = __float_as_uint(Bsb[nb * SSTR + ks * 8 + tg + 4]);
            }
#pragma unroll
            for (int mi = 0; mi < 4; mi++)
#pragma unroll
                for (int ni = 0; ni < 4; ni++) {
                    asm volatile(
                        "mma.sync.aligned.m16n8k8.row.col.f32.tf32.tf32.f32 "
                        "{%0,%1,%2,%3}, {%4,%5,%6,%7}, {%8,%9}, {%0,%1,%2,%3};"
                        : "+f"(acc[mi][ni][0]), "+f"(acc[mi][ni][1]),
                          "+f"(acc[mi][ni][2]), "+f"(acc[mi][ni][3])
                        : "r"(afr[mi][0]), "r"(afr[mi][1]), "r"(afr[mi][2]), "r"(afr[mi][3]),
                          "r"(bfr[ni][0]), "r"(bfr[ni][1]));
                }
        }
        __syncthreads();
    }

    if (wsel) {
        // xW0 -> g_u fp32, direct
#pragma unroll
        for (int mi = 0; mi < 4; mi++) {
            int rl1 = wm * 64 + mi * 16 + g;
            int rl2 = rl1 + 8;
            size_t r1 = (size_t)(row0 + rl1) * DD, r2 = (size_t)(row0 + rl2) * DD;
#pragma unroll
            for (int ni = 0; ni < 4; ni++) {
                int nc = wn * 32 + ni * 8 + tg * 2;
                float2 bv = *(const float2*)&bias[nc];
                float2 v1, v2;
                v1.x = acc[mi][ni][0] + bv.x; v1.y = acc[mi][ni][1] + bv.y;
                v2.x = acc[mi][ni][2] + bv.x; v2.y = acc[mi][ni][3] + bv.y;
                *(float2*)&g_u[r1 + col0 + nc] = v1;
                *(float2*)&g_u[r2 + col0 + nc] = v2;
            }
        }
    } else {
        // xWr -> bf16 transposed via smem staging: St[n=128][r=128], stride 136 bf16
        __nv_bfloat16* St = (__nv_bfloat16*)smf;
#pragma unroll
        for (int mi = 0; mi < 4; mi++) {
            int rl1 = wm * 64 + mi * 16 + g;
            int rl2 = rl1 + 8;
#pragma unroll
            for (int ni = 0; ni < 4; ni++) {
                int nc = wn * 32 + ni * 8 + tg * 2;
                float2 bv = *(const float2*)&bias[nc];
                St[(nc    ) * 136 + rl1] = __float2bfloat16(acc[mi][ni][0] + bv.x);
                St[(nc + 1) * 136 + rl1] = __float2bfloat16(acc[mi][ni][1] + bv.y);
                St[(nc    ) * 136 + rl2] = __float2bfloat16(acc[mi][ni][2] + bv.x);
                St[(nc + 1) * 136 + rl2] = __float2bfloat16(acc[mi][ni][3] + bv.y);
            }
        }
        __syncthreads();
        const int b   = row0 >> 11;
        const int rb0 = row0 & (NNODE - 1);
#pragma unroll
        for (int it = 0; it < 8; it++) {
            int idx = tid + it * 256;       // 0..2047
            int n   = idx >> 4;             // 0..127
            int f4  = idx & 15;             // 16 float4 per 128-bf16 row
            float4 v = *(const float4*)&St[n * 136 + f4 * 8];
            *(float4*)&g_thT[((size_t)(b * DD + col0 + n)) * NNODE + rb0 + f4 * 8] = v;
        }
    }
}

// ---------------------------------------------------------------------------
// Big batched GEMM via bf16 mma.sync m16n8k16:
//   C[b][row][n] = sum_k adjh[b][row][k] * thT[b][n][k]
// CTA 128x128, KT=64, double-buffered cp.async; both operands k-contiguous
// bf16 rows, smem stride 36 words (72 bf16) -> conflict-free fragments.
// Epilogue fp32: relu((C+u)/denom) (+nodes on last layer).
// ---------------------------------------------------------------------------
#define KT 64
#define NT_ITERS (NNODE / KT)        // 32
#define HSTR 36                      // words per 64-bf16 row (128B + 16B pad)
#define H_WORDS (128 * HSTR)         // 4608 words per operand per stage
#define SMEM_BIG (4 * H_WORDS * 4)   // 73728 bytes

__global__ void __launch_bounds__(256, 2) big_gemm_bf16(
    const float* __restrict__ nodes, float* __restrict__ out, int last)
{
    extern __shared__ float smf[];
    const int tid = threadIdx.x;
    const int lane = tid & 31, wid = tid >> 5;
    const int wm = wid >> 2, wn = wid & 3;
    const int mt = blockIdx.x, nt = blockIdx.y, b = blockIdx.z;

    const __nv_bfloat16* Ah = g_adjh + (size_t)b * NNODE * NNODE + (size_t)mt * 128 * NNODE;
    const __nv_bfloat16* Bh = g_thT + ((size_t)b * DD + nt * 128) * NNODE;

    float* AsBase = smf;
    float* BsBase = smf + 2 * H_WORDS;
    const uint32_t sA = smem_u32(AsBase);
    const uint32_t sB = smem_u32(BsBase);

    float acc[4][4][4];
#pragma unroll
    for (int mi = 0; mi < 4; mi++)
#pragma unroll
        for (int ni = 0; ni < 4; ni++)
#pragma unroll
            for (int q = 0; q < 4; q++) acc[mi][ni][q] = 0.f;

    // loaders: each operand 128 rows x 8 x16B segments = 1024 cp16 / 256 thr
    int lrow[4], lsg[4];
#pragma unroll
    for (int i = 0; i < 4; i++) {
        int idx = tid + i * 256;
        lrow[i] = idx >> 3;  lsg[i] = (idx & 7) * 8;   // bf16 offset 0..56
    }

    auto issue_tile = [&](int k0, int p) {
        uint32_t a0 = sA + (uint32_t)p * H_WORDS * 4;
        uint32_t b0 = sB + (uint32_t)p * H_WORDS * 4;
#pragma unroll
        for (int i = 0; i < 4; i++)
            cp16(a0 + lrow[i] * HSTR * 4 + lsg[i] * 2,
                 Ah + (size_t)lrow[i] * NNODE + k0 + lsg[i]);
#pragma unroll
        for (int i = 0; i < 4; i++)
            cp16(b0 + lrow[i] * HSTR * 4 + lsg[i] * 2,
                 Bh + (size_t)lrow[i] * NNODE + k0 + lsg[i]);
        asm volatile("cp.async.commit_group;" ::: "memory");
    };

    issue_tile(0, 0);

    const int g = lane >> 2, tg = lane & 3;

    for (int t = 0; t < NT_ITERS; t++) {
        int p = t & 1;
        if (t + 1 < NT_ITERS) {
            issue_tile((t + 1) * KT, (t + 1) & 1);
            asm volatile("cp.async.wait_group 1;" ::: "memory");
        } else {
            asm volatile("cp.async.wait_group 0;" ::: "memory");
        }
        __syncthreads();

        const float* Asb = AsBase + p * H_WORDS;
        const float* Bsb = BsBase + p * H_WORDS;
#pragma unroll
        for (int ks = 0; ks < 4; ks++) {     // 4 x k16 = KT
            uint32_t afr[4][4], bfr[4][2];
#pragma unroll
            for (int mi = 0; mi < 4; mi++) {
                int rb = wm * 64 + mi * 16;
                int kc = ks * 8 + tg;        // word index within 36-word row
                afr[mi][0] = __float_as_uint(Asb[(rb + g)     * HSTR + kc]);
                afr[mi][1] = __float_as_uint(Asb[(rb + 8 + g) * HSTR + kc]);
                afr[mi][2] = __float_as_uint(Asb[(rb + g)     * HSTR + kc + 4]);
                afr[mi][3] = __float_as_uint(Asb[(rb + 8 + g) * HSTR + kc + 4]);
            }
#pragma unroll
            for (int ni = 0; ni < 4; ni++) {
                int nb = wn * 32 + ni * 8 + g;
                bfr[ni][0] = __float_as_uint(Bsb[nb * HSTR + ks * 8 + tg]);
                bfr[ni][1] = __float_as_uint(Bsb[nb * HSTR + ks * 8 + tg + 4]);
            }
#pragma unroll
            for (int mi = 0; mi < 4; mi++)
#pragma unroll
                for (int ni = 0; ni < 4; ni++) {
                    asm volatile(
                        "mma.sync.aligned.m16n8k16.row.col.f32.bf16.bf16.f32 "
                        "{%0,%1,%2,%3}, {%4,%5,%6,%7}, {%8,%9}, {%0,%1,%2,%3};"
                        : "+f"(acc[mi][ni][0]), "+f"(acc[mi][ni][1]),
                          "+f"(acc[mi][ni][2]), "+f"(acc[mi][ni][3])
                        : "r"(afr[mi][0]), "r"(afr[mi][1]), "r"(afr[mi][2]), "r"(afr[mi][3]),
                          "r"(bfr[ni][0]), "r"(bfr[ni][1]));
                }
        }
        __syncthreads();
    }

#pragma unroll
    for (int mi = 0; mi < 4; mi++) {
        int rl1 = wm * 64 + mi * 16 + g;
        int rl2 = rl1 + 8;
        int row1 = mt * 128 + rl1, row2 = mt * 128 + rl2;
        size_t gr1 = (size_t)b * NNODE + row1, gr2 = (size_t)b * NNODE + row2;
        float inv1 = 1.0f / g_denom[gr1];
        float inv2 = 1.0f / g_denom[gr2];
#pragma unroll
        for (int ni = 0; ni < 4; ni++) {
            int col = nt * 128 + wn * 32 + ni * 8 + tg * 2;
            size_t o1 = gr1 * DD + col, o2 = gr2 * DD + col;
            float2 u1 = *(const float2*)&g_u[o1];
            float2 u2 = *(const float2*)&g_u[o2];
            float2 v1, v2;
            v1.x = fmaxf((acc[mi][ni][0] + u1.x) * inv1, 0.f);
            v1.y = fmaxf((acc[mi][ni][1] + u1.y) * inv1, 0.f);
            v2.x = fmaxf((acc[mi][ni][2] + u2.x) * inv2, 0.f);
            v2.y = fmaxf((acc[mi][ni][3] + u2.y) * inv2, 0.f);
            if (last) {
                float2 n1 = *(const float2*)&nodes[o1];
                float2 n2 = *(const float2*)&nodes[o2];
                v1.x += n1.x; v1.y += n1.y; v2.x += n2.x; v2.y += n2.y;
                *(float2*)&out[o1] = v1;
                *(float2*)&out[o2] = v2;
            } else {
                *(float2*)&g_x[o1] = v1;
                *(float2*)&g_x[o2] = v2;
            }
        }
    }
}

// ---------------------------------------------------------------------------
extern "C" void kernel_launch(void* const* d_in, const int* in_sizes, int n_in,
                              void* d_out, int out_size) {
    const float* nodes = (const float*)d_in[0];
    const float* adj   = (const float*)d_in[1];
    const float* W0_w  = (const float*)d_in[2];
    const float* W0_b  = (const float*)d_in[3];
    const float* Wr_w  = (const float*)d_in[4];
    const float* Wr_b  = (const float*)d_in[5];
    float* out = (float*)d_out;

    static int cfg_done = 0;
    if (!cfg_done) {
        cudaFuncSetAttribute(big_gemm_bf16, cudaFuncAttributeMaxDynamicSharedMemorySize, SMEM_BIG);
        cudaFuncSetAttribute(small_mma,     cudaFuncAttributeMaxDynamicSharedMemorySize, SMEM_SMALL);
        cfg_done = 1;
    }

    denom_kernel<<<RR, 256>>>(adj);

    dim3 sgrid(RR / 128, 4);                 // 128 x 4 = 512 CTAs
    dim3 bgrid(NNODE / 128, DD / 128, BB);   // 16 x 2 x 8 = 256 CTAs

    for (int l = 0; l < 2; l++) {
        const float* wr = Wr_w + (size_t)l * DD * DD;
        const float* br = Wr_b + (size_t)l * DD;
        const float* w0 = W0_w + (size_t)l * DD * DD;
        const float* b0 = W0_b + (size_t)l * DD;
        small_mma<<<sgrid, 256, SMEM_SMALL>>>(l, nodes, wr, br, w0, b0);  // -> g_thT, g_u
        big_gemm_bf16<<<bgrid, 256, SMEM_BIG>>>(nodes, out, l == 1);
    }
}

// round 15
// speedup vs baseline: 10.5253x; 1.2013x over previous
#include <cuda_runtime.h>
#include <cuda_bf16.h>
#include <cstdint>

#define BB 8
#define NNODE 2048
#define DD 256
#define RR (BB*NNODE)   // 16384 total rows

// Scratch (allocation-free rule: device globals)
__device__ float g_u[BB*NNODE*DD];                        // xW0 (fp32)
__device__ float g_denom[RR];
__device__ __nv_bfloat16 g_adjh[(size_t)BB*NNODE*NNODE];  // adj in bf16
__device__ __nv_bfloat16 g_thT[(size_t)BB*DD*NNODE];      // xWr bf16 TRANSPOSED [b][m][r]
__device__ __nv_bfloat16 g_nodesh[BB*NNODE*DD];           // nodes in bf16
__device__ __nv_bfloat16 g_xh[BB*NNODE*DD];               // layer activations, bf16
__device__ __nv_bfloat16 g_wrh[2*DD*DD];                  // Wr bf16 (both layers)
__device__ __nv_bfloat16 g_w0h[2*DD*DD];                  // W0 bf16 (both layers)

__device__ __forceinline__ uint32_t smem_u32(const void* p) {
    uint32_t a;
    asm("{ .reg .u64 t; cvta.to.shared.u64 t, %1; cvt.u32.u64 %0, t; }" : "=r"(a) : "l"(p));
    return a;
}
__device__ __forceinline__ void cp16(uint32_t saddr, const void* gaddr) {
    asm volatile("cp.async.ca.shared.global [%0], [%1], 16;" :: "r"(saddr), "l"(gaddr) : "memory");
}
__device__ __forceinline__ void ldm4(uint32_t& r0, uint32_t& r1, uint32_t& r2, uint32_t& r3,
                                     uint32_t addr) {
    asm volatile("ldmatrix.sync.aligned.m8n8.x4.shared.b16 {%0,%1,%2,%3}, [%4];"
                 : "=r"(r0), "=r"(r1), "=r"(r2), "=r"(r3) : "r"(addr));
}
#define MMA_BF16(acc, a, b0v, b1v) \
    asm volatile( \
        "mma.sync.aligned.m16n8k16.row.col.f32.bf16.bf16.f32 " \
        "{%0,%1,%2,%3}, {%4,%5,%6,%7}, {%8,%9}, {%0,%1,%2,%3};" \
        : "+f"((acc)[0]), "+f"((acc)[1]), "+f"((acc)[2]), "+f"((acc)[3]) \
        : "r"((a)[0]), "r"((a)[1]), "r"((a)[2]), "r"((a)[3]), "r"(b0v), "r"(b1v))

// ---------------------------------------------------------------------------
// One-shot weight conversion: Wr_w, W0_w (both layers) -> bf16
// ---------------------------------------------------------------------------
__global__ void cvt_weights(const float* __restrict__ Wr, const float* __restrict__ W0) {
    int i = blockIdx.x * 256 + threadIdx.x;   // grid 512 -> 131072 elems
    g_wrh[i] = __float2bfloat16(Wr[i]);
    g_w0h[i] = __float2bfloat16(W0[i]);
}

// ---------------------------------------------------------------------------
// denom[b,n] = sum_k adj[b,n,k] + 1 ; fused adj->bf16 and nodes->bf16
// ---------------------------------------------------------------------------
__global__ void denom_kernel(const float* __restrict__ adj, const float* __restrict__ nodes) {
    __shared__ float red[8];
    int row = blockIdx.x;
    const float4* a = (const float4*)(adj + (size_t)row * NNODE);
    uint2* ah = (uint2*)(g_adjh + (size_t)row * NNODE);
    float s = 0.f;
#pragma unroll
    for (int i = 0; i < 2; i++) {
        int f = threadIdx.x + i * 256;
        float4 v = a[f];
        s += (v.x + v.y) + (v.z + v.w);
        __nv_bfloat162 lo = __float22bfloat162_rn(make_float2(v.x, v.y));
        __nv_bfloat162 hi = __float22bfloat162_rn(make_float2(v.z, v.w));
        uint2 pk;
        pk.x = *(uint32_t*)&lo;  pk.y = *(uint32_t*)&hi;
        ah[f] = pk;
    }
    // nodes row -> bf16 (256 elems, 1 per thread)
    g_nodesh[(size_t)row * DD + threadIdx.x] =
        __float2bfloat16(nodes[(size_t)row * DD + threadIdx.x]);
#pragma unroll
    for (int o = 16; o > 0; o >>= 1) s += __shfl_xor_sync(0xffffffffu, s, o);
    if ((threadIdx.x & 31) == 0) red[threadIdx.x >> 5] = s;
    __syncthreads();
    if (threadIdx.x < 8) {
        s = red[threadIdx.x];
#pragma unroll
        for (int o = 4; o > 0; o >>= 1) s += __shfl_xor_sync(0xffu, s, o);
        if (threadIdx.x == 0) g_denom[row] = s + 1.0f;
    }
}

// ---------------------------------------------------------------------------
// Shared tile geometry (both GEMMs): CTA 128x128, KT=64 bf16,
// smem row = 64 bf16 = 32 words + 4 pad = 36 words. ldmatrix conflict-free.
// ---------------------------------------------------------------------------
#define KT 64
#define HSTR 36
#define H_WORDS (128 * HSTR)          // 4608 words per operand per stage
#define SMEM_TILE (4 * H_WORDS * 4)   // 73728 bytes

// ---------------------------------------------------------------------------
// Small GEMM, bf16 m16n8k16 + ldmatrix:
//   nt<2:  xWr -> g_thT (bf16 transposed) ; nt>=2: xW0 -> g_u (fp32)
//   A = Xh [16384,256] bf16, B = Wh [n][k] bf16 (k-contiguous, no transpose)
// ---------------------------------------------------------------------------
__global__ void __launch_bounds__(256, 2) small_mma(
    int l, const float* __restrict__ br, const float* __restrict__ b0)
{
    extern __shared__ float smf[];
    const __nv_bfloat16* __restrict__ Xh = l ? g_xh : g_nodesh;

    const int tid = threadIdx.x;
    const int lane = tid & 31, wid = tid >> 5;
    const int wm = wid >> 2, wn = wid & 3;      // warp tile 64(M) x 32(N)
    const int mt = blockIdx.x, nt = blockIdx.y;

    const int row0 = mt * 128;
    const int wsel = nt >> 1;
    const int col0 = (nt & 1) * 128;
    const __nv_bfloat16* Wh = (wsel ? g_w0h : g_wrh) + (size_t)l * DD * DD + (size_t)col0 * DD;
    const float* bias = (wsel ? b0 : br) + col0;

    const uint32_t sA = smem_u32(smf);
    const uint32_t sB = sA + 2 * H_WORDS * 4;

    float acc[4][4][4];
#pragma unroll
    for (int mi = 0; mi < 4; mi++)
#pragma unroll
        for (int ni = 0; ni < 4; ni++)
#pragma unroll
            for (int q = 0; q < 4; q++) acc[mi][ni][q] = 0.f;

    int lrow[4], lsg[4];
#pragma unroll
    for (int i = 0; i < 4; i++) {
        int idx = tid + i * 256;
        lrow[i] = idx >> 3;  lsg[i] = (idx & 7) * 8;
    }

    auto issue_tile = [&](int k0, int p) {
        uint32_t a0 = sA + (uint32_t)p * H_WORDS * 4;
        uint32_t b0a = sB + (uint32_t)p * H_WORDS * 4;
#pragma unroll
        for (int i = 0; i < 4; i++)
            cp16(a0 + lrow[i] * HSTR * 4 + lsg[i] * 2,
                 Xh + (size_t)(row0 + lrow[i]) * DD + k0 + lsg[i]);
#pragma unroll
        for (int i = 0; i < 4; i++)
            cp16(b0a + lrow[i] * HSTR * 4 + lsg[i] * 2,
                 Wh + (size_t)lrow[i] * DD + k0 + lsg[i]);
        asm volatile("cp.async.commit_group;" ::: "memory");
    };

    issue_tile(0, 0);

    // ldmatrix per-lane address components
    const int arow = ((lane >> 3) & 1) * 8 + (lane & 7);
    const int acol = ((lane >> 4) & 1) * 8;
    const int brow = ((lane >> 4) & 1) * 8 + (lane & 7);
    const int bcol = ((lane >> 3) & 1) * 8;

    const int NKI = DD / KT;   // 4

    for (int t = 0; t < NKI; t++) {
        int p = t & 1;
        if (t + 1 < NKI) {
            issue_tile((t + 1) * KT, (t + 1) & 1);
            asm volatile("cp.async.wait_group 1;" ::: "memory");
        } else {
            asm volatile("cp.async.wait_group 0;" ::: "memory");
        }
        __syncthreads();

        uint32_t aBase = sA + (uint32_t)p * H_WORDS * 4;
        uint32_t bBase = sB + (uint32_t)p * H_WORDS * 4;
#pragma unroll
        for (int ks = 0; ks < 4; ks++) {
            uint32_t afr[4][4], bfr[4][2];
#pragma unroll
            for (int mi = 0; mi < 4; mi++) {
                uint32_t ad = aBase + (uint32_t)(wm * 64 + mi * 16 + arow) * (HSTR * 4)
                            + (uint32_t)(ks * 16 + acol) * 2;
                ldm4(afr[mi][0], afr[mi][1], afr[mi][2], afr[mi][3], ad);
            }
#pragma unroll
            for (int nip = 0; nip < 2; nip++) {
                uint32_t bd = bBase + (uint32_t)(wn * 32 + nip * 16 + brow) * (HSTR * 4)
                            + (uint32_t)(ks * 16 + bcol) * 2;
                ldm4(bfr[2*nip][0], bfr[2*nip][1], bfr[2*nip+1][0], bfr[2*nip+1][1], bd);
            }
#pragma unroll
            for (int mi = 0; mi < 4; mi++)
#pragma unroll
                for (int ni = 0; ni < 4; ni++)
                    MMA_BF16(acc[mi][ni], afr[mi], bfr[ni][0], bfr[ni][1]);
        }
        __syncthreads();
    }

    const int g = lane >> 2, tg = lane & 3;
    if (wsel) {
        // xW0 -> g_u fp32
#pragma unroll
        for (int mi = 0; mi < 4; mi++) {
            int rl1 = wm * 64 + mi * 16 + g;
            int rl2 = rl1 + 8;
            size_t r1 = (size_t)(row0 + rl1) * DD, r2 = (size_t)(row0 + rl2) * DD;
#pragma unroll
            for (int ni = 0; ni < 4; ni++) {
                int nc = wn * 32 + ni * 8 + tg * 2;
                float2 bv = *(const float2*)&bias[nc];
                float2 v1, v2;
                v1.x = acc[mi][ni][0] + bv.x; v1.y = acc[mi][ni][1] + bv.y;
                v2.x = acc[mi][ni][2] + bv.x; v2.y = acc[mi][ni][3] + bv.y;
                *(float2*)&g_u[r1 + col0 + nc] = v1;
                *(float2*)&g_u[r2 + col0 + nc] = v2;
            }
        }
    } else {
        // xWr -> bf16 transposed via smem staging: St[n=128][r=128], stride 136
        __nv_bfloat16* St = (__nv_bfloat16*)smf;
#pragma unroll
        for (int mi = 0; mi < 4; mi++) {
            int rl1 = wm * 64 + mi * 16 + g;
            int rl2 = rl1 + 8;
#pragma unroll
            for (int ni = 0; ni < 4; ni++) {
                int nc = wn * 32 + ni * 8 + tg * 2;
                float2 bv = *(const float2*)&bias[nc];
                St[(nc    ) * 136 + rl1] = __float2bfloat16(acc[mi][ni][0] + bv.x);
                St[(nc + 1) * 136 + rl1] = __float2bfloat16(acc[mi][ni][1] + bv.y);
                St[(nc    ) * 136 + rl2] = __float2bfloat16(acc[mi][ni][2] + bv.x);
                St[(nc + 1) * 136 + rl2] = __float2bfloat16(acc[mi][ni][3] + bv.y);
            }
        }
        __syncthreads();
        const int b   = row0 >> 11;
        const int rb0 = row0 & (NNODE - 1);
#pragma unroll
        for (int it = 0; it < 8; it++) {
            int idx = tid + it * 256;
            int n   = idx >> 4;
            int f4  = idx & 15;
            float4 v = *(const float4*)&St[n * 136 + f4 * 8];
            *(float4*)&g_thT[((size_t)(b * DD + col0 + n)) * NNODE + rb0 + f4 * 8] = v;
        }
    }
}

// ---------------------------------------------------------------------------
// Big batched GEMM, bf16 m16n8k16 + ldmatrix:
//   C[b][row][n] = sum_k adjh[b][row][k] * thT[b][n][k]
// Epilogue fp32: relu((C+u)/denom); last layer: out = nodes + x (fp32),
// else g_xh (bf16).
// ---------------------------------------------------------------------------
#define NT_ITERS (NNODE / KT)        // 32

__global__ void __launch_bounds__(256, 2) big_gemm_bf16(
    const float* __restrict__ nodes, float* __restrict__ out, int last)
{
    extern __shared__ float smf[];
    const int tid = threadIdx.x;
    const int lane = tid & 31, wid = tid >> 5;
    const int wm = wid >> 2, wn = wid & 3;
    const int mt = blockIdx.x, nt = blockIdx.y, b = blockIdx.z;

    const __nv_bfloat16* Ah = g_adjh + (size_t)b * NNODE * NNODE + (size_t)mt * 128 * NNODE;
    const __nv_bfloat16* Bh = g_thT + ((size_t)b * DD + nt * 128) * NNODE;

    const uint32_t sA = smem_u32(smf);
    const uint32_t sB = sA + 2 * H_WORDS * 4;

    float acc[4][4][4];
#pragma unroll
    for (int mi = 0; mi < 4; mi++)
#pragma unroll
        for (int ni = 0; ni < 4; ni++)
#pragma unroll
            for (int q = 0; q < 4; q++) acc[mi][ni][q] = 0.f;

    int lrow[4], lsg[4];
#pragma unroll
    for (int i = 0; i < 4; i++) {
        int idx = tid + i * 256;
        lrow[i] = idx >> 3;  lsg[i] = (idx & 7) * 8;
    }

    auto issue_tile = [&](int k0, int p) {
        uint32_t a0 = sA + (uint32_t)p * H_WORDS * 4;
        uint32_t b0 = sB + (uint32_t)p * H_WORDS * 4;
#pragma unroll
        for (int i = 0; i < 4; i++)
            cp16(a0 + lrow[i] * HSTR * 4 + lsg[i] * 2,
                 Ah + (size_t)lrow[i] * NNODE + k0 + lsg[i]);
#pragma unroll
        for (int i = 0; i < 4; i++)
            cp16(b0 + lrow[i] * HSTR * 4 + lsg[i] * 2,
                 Bh + (size_t)lrow[i] * NNODE + k0 + lsg[i]);
        asm volatile("cp.async.commit_group;" ::: "memory");
    };

    issue_tile(0, 0);

    const int arow = ((lane >> 3) & 1) * 8 + (lane & 7);
    const int acol = ((lane >> 4) & 1) * 8;
    const int brow = ((lane >> 4) & 1) * 8 + (lane & 7);
    const int bcol = ((lane >> 3) & 1) * 8;

    for (int t = 0; t < NT_ITERS; t++) {
        int p = t & 1;
        if (t + 1 < NT_ITERS) {
            issue_tile((t + 1) * KT, (t + 1) & 1);
            asm volatile("cp.async.wait_group 1;" ::: "memory");
        } else {
            asm volatile("cp.async.wait_group 0;" ::: "memory");
        }
        __syncthreads();

        uint32_t aBase = sA + (uint32_t)p * H_WORDS * 4;
        uint32_t bBase = sB + (uint32_t)p * H_WORDS * 4;
#pragma unroll
        for (int ks = 0; ks < 4; ks++) {
            uint32_t afr[4][4], bfr[4][2];
#pragma unroll
            for (int mi = 0; mi < 4; mi++) {
                uint32_t ad = aBase + (uint32_t)(wm * 64 + mi * 16 + arow) * (HSTR * 4)
                            + (uint32_t)(ks * 16 + acol) * 2;
                ldm4(afr[mi][0], afr[mi][1], afr[mi][2], afr[mi][3], ad);
            }
#pragma unroll
            for (int nip = 0; nip < 2; nip++) {
                uint32_t bd = bBase + (uint32_t)(wn * 32 + nip * 16 + brow) * (HSTR * 4)
                            + (uint32_t)(ks * 16 + bcol) * 2;
                ldm4(bfr[2*nip][0], bfr[2*nip][1], bfr[2*nip+1][0], bfr[2*nip+1][1], bd);
            }
#pragma unroll
            for (int mi = 0; mi < 4; mi++)
#pragma unroll
                for (int ni = 0; ni < 4; ni++)
                    MMA_BF16(acc[mi][ni], afr[mi], bfr[ni][0], bfr[ni][1]);
        }
        __syncthreads();
    }

    const int g = lane >> 2, tg = lane & 3;
#pragma unroll
    for (int mi = 0; mi < 4; mi++) {
        int rl1 = wm * 64 + mi * 16 + g;
        int rl2 = rl1 + 8;
        int row1 = mt * 128 + rl1, row2 = mt * 128 + rl2;
        size_t gr1 = (size_t)b * NNODE + row1, gr2 = (size_t)b * NNODE + row2;
        float inv1 = 1.0f / g_denom[gr1];
        float inv2 = 1.0f / g_denom[gr2];
#pragma unroll
        for (int ni = 0; ni < 4; ni++) {
            int col = nt * 128 + wn * 32 + ni * 8 + tg * 2;
            size_t o1 = gr1 * DD + col, o2 = gr2 * DD + col;
            float2 u1 = *(const float2*)&g_u[o1];
            float2 u2 = *(const float2*)&g_u[o2];
            float2 v1, v2;
            v1.x = fmaxf((acc[mi][ni][0] + u1.x) * inv1, 0.f);
            v1.y = fmaxf((acc[mi][ni][1] + u1.y) * inv1, 0.f);
            v2.x = fmaxf((acc[mi][ni][2] + u2.x) * inv2, 0.f);
            v2.y = fmaxf((acc[mi][ni][3] + u2.y) * inv2, 0.f);
            if (last) {
                float2 n1 = *(const float2*)&nodes[o1];
                float2 n2 = *(const float2*)&nodes[o2];
                v1.x += n1.x; v1.y += n1.y; v2.x += n2.x; v2.y += n2.y;
                *(float2*)&out[o1] = v1;
                *(float2*)&out[o2] = v2;
            } else {
                __nv_bfloat162 h1 = __float22bfloat162_rn(v1);
                __nv_bfloat162 h2 = __float22bfloat162_rn(v2);
                *(__nv_bfloat162*)&g_xh[o1] = h1;
                *(__nv_bfloat162*)&g_xh[o2] = h2;
            }
        }
    }
}

// ---------------------------------------------------------------------------
extern "C" void kernel_launch(void* const* d_in, const int* in_sizes, int n_in,
                              void* d_out, int out_size) {
    const float* nodes = (const float*)d_in[0];
    const float* adj   = (const float*)d_in[1];
    const float* W0_w  = (const float*)d_in[2];
    const float* W0_b  = (const float*)d_in[3];
    const float* Wr_w  = (const float*)d_in[4];
    const float* Wr_b  = (const float*)d_in[5];
    float* out = (float*)d_out;

    static int cfg_done = 0;
    if (!cfg_done) {
        cudaFuncSetAttribute(big_gemm_bf16, cudaFuncAttributeMaxDynamicSharedMemorySize, SMEM_TILE);
        cudaFuncSetAttribute(small_mma,     cudaFuncAttributeMaxDynamicSharedMemorySize, SMEM_TILE);
        cfg_done = 1;
    }

    cvt_weights<<<512, 256>>>(Wr_w, W0_w);
    denom_kernel<<<RR, 256>>>(adj, nodes);

    dim3 sgrid(RR / 128, 4);                 // 128 x 4 = 512 CTAs
    dim3 bgrid(NNODE / 128, DD / 128, BB);   // 16 x 2 x 8 = 256 CTAs

    for (int l = 0; l < 2; l++) {
        const float* br = Wr_b + (size_t)l * DD;
        const float* b0 = W0_b + (size_t)l * DD;
        small_mma<<<sgrid, 256, SMEM_TILE>>>(l, br, b0);          // -> g_thT, g_u
        big_gemm_bf16<<<bgrid, 256, SMEM_TILE>>>(nodes, out, l == 1);
    }
}